// round 5
// baseline (speedup 1.0000x reference)
#include <cuda_runtime.h>
#include <cuda_bf16.h>
#include <math.h>
#include <stdint.h>

#define HID    1024
#define NHEADS 16
#define HDIM   64
#define SEQ    2048
#define BATCH  2
#define TOKS   (BATCH*SEQ)   // 4096
#define NELEM  (BATCH*NHEADS*SEQ*HDIM)

// bf16 hi/lo scratch, [B, NH, S, HD]. Q pre-scaled by 1/sqrt(HD).
__device__ __align__(16) __nv_bfloat16 g_Qh[NELEM], g_Ql[NELEM];
__device__ __align__(16) __nv_bfloat16 g_Kh[NELEM], g_Kl[NELEM];
__device__ __align__(16) __nv_bfloat16 g_Vh[NELEM], g_Vl[NELEM];

// ===================== helpers =====================
__device__ __forceinline__ uint32_t smem_u32(const void* p) {
    uint32_t a;
    asm("{ .reg .u64 t; cvta.to.shared.u64 t, %1; cvt.u32.u64 %0, t; }"
        : "=r"(a) : "l"(p));
    return a;
}
__device__ __forceinline__ void ldsm4(uint32_t* r, uint32_t a) {
    asm volatile("ldmatrix.sync.aligned.m8n8.x4.shared.b16 {%0,%1,%2,%3}, [%4];"
        : "=r"(r[0]), "=r"(r[1]), "=r"(r[2]), "=r"(r[3]) : "r"(a));
}
__device__ __forceinline__ void ldsm4t(uint32_t* r, uint32_t a) {
    asm volatile("ldmatrix.sync.aligned.m8n8.x4.trans.shared.b16 {%0,%1,%2,%3}, [%4];"
        : "=r"(r[0]), "=r"(r[1]), "=r"(r[2]), "=r"(r[3]) : "r"(a));
}
__device__ __forceinline__ void mma16816(float* d, const uint32_t* a, const uint32_t* b) {
    asm volatile(
        "mma.sync.aligned.m16n8k16.row.col.f32.bf16.bf16.f32 "
        "{%0,%1,%2,%3}, {%4,%5,%6,%7}, {%8,%9}, {%0,%1,%2,%3};"
        : "+f"(d[0]), "+f"(d[1]), "+f"(d[2]), "+f"(d[3])
        : "r"(a[0]), "r"(a[1]), "r"(a[2]), "r"(a[3]), "r"(b[0]), "r"(b[1]));
}
__device__ __forceinline__ uint32_t pack_hi(float x, float y) {
    __nv_bfloat162 h = __floats2bfloat162_rn(x, y);
    return *reinterpret_cast<uint32_t*>(&h);
}
__device__ __forceinline__ uint32_t pack_lo(float x, float y, uint32_t hi) {
    __nv_bfloat162 h = *reinterpret_cast<__nv_bfloat162*>(&hi);
    return pack_hi(x - __bfloat162float(h.x), y - __bfloat162float(h.y));
}
__device__ __forceinline__ void cpa16(uint32_t s, const void* g) {
    asm volatile("{\n\t.reg .u64 gp;\n\tcvta.to.global.u64 gp, %1;\n\t"
                 "cp.async.cg.shared.global [%0], [gp], 16;\n\t}"
                 :: "r"(s), "l"(g) : "memory");
}
#define CP_COMMIT() asm volatile("cp.async.commit_group;" ::: "memory")
#define CP_WAIT1()  asm volatile("cp.async.wait_group 1;" ::: "memory")
#define CP_WAIT0()  asm volatile("cp.async.wait_group 0;" ::: "memory")

// ===========================================================================
// Kernel 1: QKV projection, mma.sync bf16 hi/lo split (hh+hl+lh).
// CTA 128x128, BK=32, 8 warps (64x32 each). Register-prefetch next K tile.
// Epilogue writes bf16 hi/lo scratch (Q pre-scaled by 0.125).
// ===========================================================================
#define AP 40

__global__ __launch_bounds__(256)
void qkv_mma(const float* __restrict__ hidden,
             const float* __restrict__ Wq, const float* __restrict__ bq,
             const float* __restrict__ Wk, const float* __restrict__ bk,
             const float* __restrict__ Wv, const float* __restrict__ bv)
{
    __shared__ __nv_bfloat16 sAh[128*AP], sAl[128*AP];
    __shared__ __nv_bfloat16 sBh[128*AP], sBl[128*AP];

    const int z = blockIdx.z;
    const float* W    = (z == 0) ? Wq : ((z == 1) ? Wk : Wv);
    const float* bias = (z == 0) ? bq : ((z == 1) ? bk : bv);
    __nv_bfloat16* dstH = (z == 0) ? g_Qh : ((z == 1) ? g_Kh : g_Vh);
    __nv_bfloat16* dstL = (z == 0) ? g_Ql : ((z == 1) ? g_Kl : g_Vl);
    const float oscale = (z == 0) ? 0.125f : 1.0f;

    const int tid  = threadIdx.x;
    const int lane = tid & 31;
    const int wid  = tid >> 5;
    const int wm   = wid >> 2;
    const int wn   = wid & 3;
    const int m0   = blockIdx.y * 128;
    const int n0   = blockIdx.x * 128;

    const uint32_t aAh = smem_u32(sAh), aAl = smem_u32(sAl);
    const uint32_t aBh = smem_u32(sBh), aBl = smem_u32(sBl);

    const int lrow = tid >> 3;          // +32*r
    const int lc   = (tid & 7) * 4;

    float acc[4][4][4];
    #pragma unroll
    for (int mt = 0; mt < 4; mt++)
        #pragma unroll
        for (int nt = 0; nt < 4; nt++)
            #pragma unroll
            for (int q = 0; q < 4; q++) acc[mt][nt][q] = 0.0f;

    // prefetch tile kt=0
    float4 pa[4], pw[4];
    #pragma unroll
    for (int r = 0; r < 4; r++) {
        int row = lrow + r * 32;
        pa[r] = *(const float4*)&hidden[(size_t)(m0 + row) * HID + lc];
        pw[r] = *(const float4*)&W[(size_t)(n0 + row) * HID + lc];
    }

    for (int kt = 0; kt < HID; kt += 32) {
        // convert + store current tile
        #pragma unroll
        for (int r = 0; r < 4; r++) {
            int row = lrow + r * 32;
            uint32_t h0 = pack_hi(pa[r].x, pa[r].y), h1 = pack_hi(pa[r].z, pa[r].w);
            *(uint2*)&sAh[row * AP + lc] = make_uint2(h0, h1);
            *(uint2*)&sAl[row * AP + lc] =
                make_uint2(pack_lo(pa[r].x, pa[r].y, h0), pack_lo(pa[r].z, pa[r].w, h1));
            uint32_t g0 = pack_hi(pw[r].x, pw[r].y), g1 = pack_hi(pw[r].z, pw[r].w);
            *(uint2*)&sBh[row * AP + lc] = make_uint2(g0, g1);
            *(uint2*)&sBl[row * AP + lc] =
                make_uint2(pack_lo(pw[r].x, pw[r].y, g0), pack_lo(pw[r].z, pw[r].w, g1));
        }
        __syncthreads();

        // prefetch next tile (LDGs overlap MMAs below)
        if (kt + 32 < HID) {
            #pragma unroll
            for (int r = 0; r < 4; r++) {
                int row = lrow + r * 32;
                pa[r] = *(const float4*)&hidden[(size_t)(m0 + row) * HID + kt + 32 + lc];
                pw[r] = *(const float4*)&W[(size_t)(n0 + row) * HID + kt + 32 + lc];
            }
        }

        #pragma unroll
        for (int ks = 0; ks < 2; ks++) {
            uint32_t ah[4][4], al[4][4], bh[4][2], bl[4][2];
            const int arow = wm * 64 + (lane & 15);
            const int acol = ks * 16 + ((lane >> 4) << 3);
            #pragma unroll
            for (int mt = 0; mt < 4; mt++) {
                uint32_t off = (uint32_t)(((arow + mt * 16) * AP + acol) * 2);
                ldsm4(ah[mt], aAh + off);
                ldsm4(al[mt], aAl + off);
            }
            const int brow = wn * 32 + (lane & 7) + ((lane >> 4) << 3);
            const int bcol = ks * 16 + ((lane >> 3) & 1) * 8;
            #pragma unroll
            for (int np = 0; np < 2; np++) {
                uint32_t off = (uint32_t)(((brow + np * 16) * AP + bcol) * 2);
                uint32_t r4[4];
                ldsm4(r4, aBh + off);
                bh[np*2][0] = r4[0]; bh[np*2][1] = r4[1];
                bh[np*2+1][0] = r4[2]; bh[np*2+1][1] = r4[3];
                ldsm4(r4, aBl + off);
                bl[np*2][0] = r4[0]; bl[np*2][1] = r4[1];
                bl[np*2+1][0] = r4[2]; bl[np*2+1][1] = r4[3];
            }
            #pragma unroll
            for (int mt = 0; mt < 4; mt++)
                #pragma unroll
                for (int nt = 0; nt < 4; nt++) {
                    mma16816(acc[mt][nt], ah[mt], bh[nt]);
                    mma16816(acc[mt][nt], ah[mt], bl[nt]);
                    mma16816(acc[mt][nt], al[mt], bh[nt]);
                }
        }
        __syncthreads();
    }

    // epilogue: add bias, scale (Q), split hi/lo, scatter to bf16 scratch
    #pragma unroll
    for (int mt = 0; mt < 4; mt++) {
        int r = m0 + wm * 64 + mt * 16 + (lane >> 2);
        int b = r >> 11;
        int s = r & (SEQ - 1);
        #pragma unroll
        for (int nt = 0; nt < 4; nt++) {
            int o = n0 + wn * 32 + nt * 8 + 2 * (lane & 3);
            int h = o >> 6;
            int d = o & (HDIM - 1);
            size_t p = (((size_t)b * NHEADS + h) * SEQ + s) * HDIM + d;
            float x0 = (acc[mt][nt][0] + bias[o])     * oscale;
            float x1 = (acc[mt][nt][1] + bias[o + 1]) * oscale;
            float x2 = (acc[mt][nt][2] + bias[o])     * oscale;
            float x3 = (acc[mt][nt][3] + bias[o + 1]) * oscale;
            uint32_t h01 = pack_hi(x0, x1), h23 = pack_hi(x2, x3);
            *(uint32_t*)&dstH[p] = h01;
            *(uint32_t*)&dstL[p] = pack_lo(x0, x1, h01);
            *(uint32_t*)&dstH[p + 8 * HDIM] = h23;
            *(uint32_t*)&dstL[p + 8 * HDIM] = pack_lo(x2, x3, h23);
        }
    }
}

// ===========================================================================
// Kernel 2: flash attention, mma.sync bf16 hi/lo, cp.async double-buffered.
// CTA = 128 q-rows of one (b,h); 8 warps x 16 q-rows; 64-key tiles.
// ===========================================================================
#define KP 72
#define ARRB  (64*KP*2)     // 9216 bytes per array
#define STAGEB (4*ARRB)     // Kh,Kl,Vh,Vl
#define ATTN_SMEM (2*STAGEB)
#define NT (SEQ/64)

__global__ __launch_bounds__(256)
void attn_mma(float* __restrict__ out)
{
    extern __shared__ char smem[];
    const uint32_t sb = smem_u32(smem);

    const int tid  = threadIdx.x;
    const int lane = tid & 31;
    const int wid  = tid >> 5;
    const int q0   = blockIdx.x * 128;
    const int bh   = blockIdx.y;
    const size_t base = (size_t)bh * SEQ * HDIM;

    const int crow = tid >> 3;          // 0..31, +32 per half
    const int cch  = (tid & 7) * 8;     // bf16 col of 16B chunk

    // issue stage 0 loads
    {
        #pragma unroll
        for (int r = 0; r < 8; r++) {
            const __nv_bfloat16* g = (r < 2) ? g_Kh : (r < 4) ? g_Kl
                                   : (r < 6) ? g_Vh : g_Vl;
            int arr = r >> 1;
            int row = (r & 1) * 32 + crow;
            cpa16(sb + arr * ARRB + (uint32_t)((row * KP + cch) * 2),
                  g + base + (size_t)row * HDIM + cch);
        }
        CP_COMMIT();
    }

    // ---- Q fragments (bf16 hi/lo scratch, already scaled) ----
    const int qrow = q0 + wid * 16 + (lane >> 2);
    const int qc   = 2 * (lane & 3);
    uint32_t qh[4][4], ql[4][4];
    #pragma unroll
    for (int kt = 0; kt < 4; kt++) {
        int c = kt * 16 + qc;
        qh[kt][0] = *(const uint32_t*)&g_Qh[base + (size_t)qrow * HDIM + c];
        qh[kt][1] = *(const uint32_t*)&g_Qh[base + (size_t)(qrow + 8) * HDIM + c];
        qh[kt][2] = *(const uint32_t*)&g_Qh[base + (size_t)qrow * HDIM + c + 8];
        qh[kt][3] = *(const uint32_t*)&g_Qh[base + (size_t)(qrow + 8) * HDIM + c + 8];
        ql[kt][0] = *(const uint32_t*)&g_Ql[base + (size_t)qrow * HDIM + c];
        ql[kt][1] = *(const uint32_t*)&g_Ql[base + (size_t)(qrow + 8) * HDIM + c];
        ql[kt][2] = *(const uint32_t*)&g_Ql[base + (size_t)qrow * HDIM + c + 8];
        ql[kt][3] = *(const uint32_t*)&g_Ql[base + (size_t)(qrow + 8) * HDIM + c + 8];
    }

    float m[2] = { -INFINITY, -INFINITY };
    float l[2] = { 0.0f, 0.0f };
    float o[8][4];
    #pragma unroll
    for (int nt = 0; nt < 8; nt++)
        #pragma unroll
        for (int q = 0; q < 4; q++) o[nt][q] = 0.0f;

    for (int t = 0; t < NT; t++) {
        // issue next stage, then wait for current
        if (t + 1 < NT) {
            const uint32_t st1 = ((t + 1) & 1) * STAGEB;
            const size_t goff = base + (size_t)(t + 1) * 64 * HDIM;
            #pragma unroll
            for (int r = 0; r < 8; r++) {
                const __nv_bfloat16* g = (r < 2) ? g_Kh : (r < 4) ? g_Kl
                                       : (r < 6) ? g_Vh : g_Vl;
                int arr = r >> 1;
                int row = (r & 1) * 32 + crow;
                cpa16(sb + st1 + arr * ARRB + (uint32_t)((row * KP + cch) * 2),
                      g + goff + (size_t)row * HDIM + cch);
            }
            CP_COMMIT();
            CP_WAIT1();
        } else {
            CP_WAIT0();
        }
        __syncthreads();

        const uint32_t stg = (t & 1) * STAGEB;
        const uint32_t aKh = sb + stg;
        const uint32_t aKl = aKh + ARRB;
        const uint32_t aVh = aKl + ARRB;
        const uint32_t aVl = aVh + ARRB;

        // ---- S = Q K^T ----
        float s[8][4];
        #pragma unroll
        for (int nt = 0; nt < 8; nt++)
            #pragma unroll
            for (int q = 0; q < 4; q++) s[nt][q] = 0.0f;

        #pragma unroll
        for (int ks = 0; ks < 4; ks++) {
            const int krow = (lane & 7) + ((lane >> 4) << 3);
            const int kcol = ks * 16 + ((lane >> 3) & 1) * 8;
            #pragma unroll
            for (int np = 0; np < 4; np++) {
                uint32_t off = (uint32_t)(((krow + np * 16) * KP + kcol) * 2);
                uint32_t rh[4], rl[4];
                ldsm4(rh, aKh + off);
                ldsm4(rl, aKl + off);
                uint32_t b0h[2] = { rh[0], rh[1] }, b1h[2] = { rh[2], rh[3] };
                uint32_t b0l[2] = { rl[0], rl[1] }, b1l[2] = { rl[2], rl[3] };
                mma16816(s[np*2],   qh[ks], b0h);
                mma16816(s[np*2],   qh[ks], b0l);
                mma16816(s[np*2],   ql[ks], b0h);
                mma16816(s[np*2+1], qh[ks], b1h);
                mma16816(s[np*2+1], qh[ks], b1l);
                mma16816(s[np*2+1], ql[ks], b1h);
            }
        }

        // ---- online softmax ----
        float sc0, sc1;
        {
            float mt = -INFINITY;
            #pragma unroll
            for (int nt = 0; nt < 8; nt++)
                mt = fmaxf(mt, fmaxf(s[nt][0], s[nt][1]));
            mt = fmaxf(mt, __shfl_xor_sync(0xffffffffu, mt, 1));
            mt = fmaxf(mt, __shfl_xor_sync(0xffffffffu, mt, 2));
            float mn = fmaxf(m[0], mt);
            sc0 = __expf(m[0] - mn);
            m[0] = mn;
            float ps = 0.0f;
            #pragma unroll
            for (int nt = 0; nt < 8; nt++) {
                s[nt][0] = __expf(s[nt][0] - mn);
                s[nt][1] = __expf(s[nt][1] - mn);
                ps += s[nt][0] + s[nt][1];
            }
            ps += __shfl_xor_sync(0xffffffffu, ps, 1);
            ps += __shfl_xor_sync(0xffffffffu, ps, 2);
            l[0] = l[0] * sc0 + ps;
        }
        {
            float mt = -INFINITY;
            #pragma unroll
            for (int nt = 0; nt < 8; nt++)
                mt = fmaxf(mt, fmaxf(s[nt][2], s[nt][3]));
            mt = fmaxf(mt, __shfl_xor_sync(0xffffffffu, mt, 1));
            mt = fmaxf(mt, __shfl_xor_sync(0xffffffffu, mt, 2));
            float mn = fmaxf(m[1], mt);
            sc1 = __expf(m[1] - mn);
            m[1] = mn;
            float ps = 0.0f;
            #pragma unroll
            for (int nt = 0; nt < 8; nt++) {
                s[nt][2] = __expf(s[nt][2] - mn);
                s[nt][3] = __expf(s[nt][3] - mn);
                ps += s[nt][2] + s[nt][3];
            }
            ps += __shfl_xor_sync(0xffffffffu, ps, 1);
            ps += __shfl_xor_sync(0xffffffffu, ps, 2);
            l[1] = l[1] * sc1 + ps;
        }
        #pragma unroll
        for (int nt = 0; nt < 8; nt++) {
            o[nt][0] *= sc0; o[nt][1] *= sc0;
            o[nt][2] *= sc1; o[nt][3] *= sc1;
        }

        // ---- P repack (C-frag -> A-frag, registers only) ----
        uint32_t ph[4][4], pl[4][4];
        #pragma unroll
        for (int kp = 0; kp < 4; kp++) {
            const int t0 = 2 * kp, t1 = 2 * kp + 1;
            ph[kp][0] = pack_hi(s[t0][0], s[t0][1]); pl[kp][0] = pack_lo(s[t0][0], s[t0][1], ph[kp][0]);
            ph[kp][1] = pack_hi(s[t0][2], s[t0][3]); pl[kp][1] = pack_lo(s[t0][2], s[t0][3], ph[kp][1]);
            ph[kp][2] = pack_hi(s[t1][0], s[t1][1]); pl[kp][2] = pack_lo(s[t1][0], s[t1][1], ph[kp][2]);
            ph[kp][3] = pack_hi(s[t1][2], s[t1][3]); pl[kp][3] = pack_lo(s[t1][2], s[t1][3], ph[kp][3]);
        }

        // ---- O += P V ----
        #pragma unroll
        for (int kp = 0; kp < 4; kp++) {
            const int vrow = kp * 16 + (lane & 7) + (((lane >> 3) & 1) << 3);
            #pragma unroll
            for (int np = 0; np < 4; np++) {
                const int vcol = np * 16 + ((lane >> 4) << 3);
                uint32_t off = (uint32_t)((vrow * KP + vcol) * 2);
                uint32_t rh[4], rl[4];
                ldsm4t(rh, aVh + off);
                ldsm4t(rl, aVl + off);
                uint32_t b0h[2] = { rh[0], rh[1] }, b1h[2] = { rh[2], rh[3] };
                uint32_t b0l[2] = { rl[0], rl[1] }, b1l[2] = { rl[2], rl[3] };
                mma16816(o[np*2],   ph[kp], b0h);
                mma16816(o[np*2],   ph[kp], b0l);
                mma16816(o[np*2],   pl[kp], b0h);
                mma16816(o[np*2+1], ph[kp], b1h);
                mma16816(o[np*2+1], ph[kp], b1l);
                mma16816(o[np*2+1], pl[kp], b1h);
            }
        }
        __syncthreads();   // done reading stage t before it is overwritten
    }

    // ---- epilogue ----
    const int b = bh >> 4;
    const int h = bh & (NHEADS - 1);
    const float inv0 = 1.0f / l[0];
    const float inv1 = 1.0f / l[1];
    const int r = q0 + wid * 16 + (lane >> 2);
    #pragma unroll
    for (int nt = 0; nt < 8; nt++) {
        int d = nt * 8 + 2 * (lane & 3);
        *(float2*)&out[((size_t)b * SEQ + r) * HID + h * HDIM + d] =
            make_float2(o[nt][0] * inv0, o[nt][1] * inv0);
        *(float2*)&out[((size_t)b * SEQ + r + 8) * HID + h * HDIM + d] =
            make_float2(o[nt][2] * inv1, o[nt][3] * inv1);
    }
}

// ---------------------------------------------------------------------------
extern "C" void kernel_launch(void* const* d_in, const int* in_sizes, int n_in,
                              void* d_out, int out_size)
{
    const float* hidden = (const float*)d_in[0];
    const float* Wq = (const float*)d_in[1];
    const float* bq = (const float*)d_in[2];
    const float* Wk = (const float*)d_in[3];
    const float* bk = (const float*)d_in[4];
    const float* Wv = (const float*)d_in[5];
    const float* bv = (const float*)d_in[6];
    float* out = (float*)d_out;

    qkv_mma<<<dim3(HID / 128, TOKS / 128, 3), 256>>>(hidden, Wq, bq, Wk, bk, Wv, bv);

    cudaFuncSetAttribute(attn_mma, cudaFuncAttributeMaxDynamicSharedMemorySize, ATTN_SMEM);
    attn_mma<<<dim3(SEQ / 128, BATCH * NHEADS), 256, ATTN_SMEM>>>(out);
}

// round 6
// speedup vs baseline: 1.1105x; 1.1105x over previous
#include <cuda_runtime.h>
#include <cuda_bf16.h>
#include <math.h>
#include <stdint.h>

#define HID    1024
#define NHEADS 16
#define HDIM   64
#define SEQ    2048
#define BATCH  2
#define TOKS   (BATCH*SEQ)   // 4096
#define NELEM  (BATCH*NHEADS*SEQ*HDIM)

// bf16 hi/lo scratch, [B, NH, S, HD]. Q pre-scaled by log2(e)/sqrt(HD).
__device__ __align__(16) __nv_bfloat16 g_Qh[NELEM], g_Ql[NELEM];
__device__ __align__(16) __nv_bfloat16 g_Kh[NELEM], g_Kl[NELEM];
__device__ __align__(16) __nv_bfloat16 g_Vh[NELEM], g_Vl[NELEM];

// ===================== helpers =====================
__device__ __forceinline__ uint32_t smem_u32(const void* p) {
    uint32_t a;
    asm("{ .reg .u64 t; cvta.to.shared.u64 t, %1; cvt.u32.u64 %0, t; }"
        : "=r"(a) : "l"(p));
    return a;
}
__device__ __forceinline__ void ldsm4(uint32_t* r, uint32_t a) {
    asm volatile("ldmatrix.sync.aligned.m8n8.x4.shared.b16 {%0,%1,%2,%3}, [%4];"
        : "=r"(r[0]), "=r"(r[1]), "=r"(r[2]), "=r"(r[3]) : "r"(a));
}
__device__ __forceinline__ void ldsm4t(uint32_t* r, uint32_t a) {
    asm volatile("ldmatrix.sync.aligned.m8n8.x4.trans.shared.b16 {%0,%1,%2,%3}, [%4];"
        : "=r"(r[0]), "=r"(r[1]), "=r"(r[2]), "=r"(r[3]) : "r"(a));
}
__device__ __forceinline__ void mma16816(float* d, const uint32_t* a, const uint32_t* b) {
    asm volatile(
        "mma.sync.aligned.m16n8k16.row.col.f32.bf16.bf16.f32 "
        "{%0,%1,%2,%3}, {%4,%5,%6,%7}, {%8,%9}, {%0,%1,%2,%3};"
        : "+f"(d[0]), "+f"(d[1]), "+f"(d[2]), "+f"(d[3])
        : "r"(a[0]), "r"(a[1]), "r"(a[2]), "r"(a[3]), "r"(b[0]), "r"(b[1]));
}
__device__ __forceinline__ uint32_t pack_hi(float x, float y) {
    __nv_bfloat162 h = __floats2bfloat162_rn(x, y);
    return *reinterpret_cast<uint32_t*>(&h);
}
__device__ __forceinline__ uint32_t pack_lo(float x, float y, uint32_t hi) {
    __nv_bfloat162 h = *reinterpret_cast<__nv_bfloat162*>(&hi);
    return pack_hi(x - __bfloat162float(h.x), y - __bfloat162float(h.y));
}
__device__ __forceinline__ void cpa16(uint32_t s, const void* g) {
    asm volatile("{\n\t.reg .u64 gp;\n\tcvta.to.global.u64 gp, %1;\n\t"
                 "cp.async.cg.shared.global [%0], [gp], 16;\n\t}"
                 :: "r"(s), "l"(g) : "memory");
}
#define CP_COMMIT() asm volatile("cp.async.commit_group;" ::: "memory")
#define CP_WAIT1()  asm volatile("cp.async.wait_group 1;" ::: "memory")
#define CP_WAIT0()  asm volatile("cp.async.wait_group 0;" ::: "memory")

// ===========================================================================
// Kernel 1: QKV projection, mma.sync bf16 hi/lo split (hh+hl+lh).
// CTA 128x128, BK=32, 8 warps. 2 CTAs/SM. Direct LDG->convert->STS staging.
// Epilogue writes bf16 hi/lo scratch (Q pre-scaled by 0.125*log2e).
// ===========================================================================
#define AP 40

__global__ __launch_bounds__(256, 2)
void qkv_mma(const float* __restrict__ hidden,
             const float* __restrict__ Wq, const float* __restrict__ bq,
             const float* __restrict__ Wk, const float* __restrict__ bk,
             const float* __restrict__ Wv, const float* __restrict__ bv)
{
    __shared__ __nv_bfloat16 sAh[128*AP], sAl[128*AP];
    __shared__ __nv_bfloat16 sBh[128*AP], sBl[128*AP];

    const int z = blockIdx.z;
    const float* W    = (z == 0) ? Wq : ((z == 1) ? Wk : Wv);
    const float* bias = (z == 0) ? bq : ((z == 1) ? bk : bv);
    __nv_bfloat16* dstH = (z == 0) ? g_Qh : ((z == 1) ? g_Kh : g_Vh);
    __nv_bfloat16* dstL = (z == 0) ? g_Ql : ((z == 1) ? g_Kl : g_Vl);
    const float oscale = (z == 0) ? 0.125f * 1.4426950408889634f : 1.0f;

    const int tid  = threadIdx.x;
    const int lane = tid & 31;
    const int wid  = tid >> 5;
    const int wm   = wid >> 2;
    const int wn   = wid & 3;
    const int m0   = blockIdx.y * 128;
    const int n0   = blockIdx.x * 128;

    const uint32_t aAh = smem_u32(sAh), aAl = smem_u32(sAl);
    const uint32_t aBh = smem_u32(sBh), aBl = smem_u32(sBl);

    float acc[4][4][4];
    #pragma unroll
    for (int mt = 0; mt < 4; mt++)
        #pragma unroll
        for (int nt = 0; nt < 4; nt++)
            #pragma unroll
            for (int q = 0; q < 4; q++) acc[mt][nt][q] = 0.0f;

    for (int kt = 0; kt < HID; kt += 32) {
        #pragma unroll
        for (int r = 0; r < 4; r++) {
            int idx = tid + r * 256;            // 0..1023
            int row = idx >> 3;                 // 0..127
            int c   = (idx & 7) * 4;            // 0..28
            float4 a = *(const float4*)&hidden[(size_t)(m0 + row) * HID + kt + c];
            uint32_t h0 = pack_hi(a.x, a.y), h1 = pack_hi(a.z, a.w);
            *(uint2*)&sAh[row * AP + c] = make_uint2(h0, h1);
            *(uint2*)&sAl[row * AP + c] =
                make_uint2(pack_lo(a.x, a.y, h0), pack_lo(a.z, a.w, h1));
            float4 w = *(const float4*)&W[(size_t)(n0 + row) * HID + kt + c];
            uint32_t g0 = pack_hi(w.x, w.y), g1 = pack_hi(w.z, w.w);
            *(uint2*)&sBh[row * AP + c] = make_uint2(g0, g1);
            *(uint2*)&sBl[row * AP + c] =
                make_uint2(pack_lo(w.x, w.y, g0), pack_lo(w.z, w.w, g1));
        }
        __syncthreads();

        #pragma unroll
        for (int ks = 0; ks < 2; ks++) {
            uint32_t ah[4][4], al[4][4], bh[4][2], bl[4][2];
            const int arow = wm * 64 + (lane & 15);
            const int acol = ks * 16 + ((lane >> 4) << 3);
            #pragma unroll
            for (int mt = 0; mt < 4; mt++) {
                uint32_t off = (uint32_t)(((arow + mt * 16) * AP + acol) * 2);
                ldsm4(ah[mt], aAh + off);
                ldsm4(al[mt], aAl + off);
            }
            const int brow = wn * 32 + (lane & 7) + ((lane >> 4) << 3);
            const int bcol = ks * 16 + ((lane >> 3) & 1) * 8;
            #pragma unroll
            for (int np = 0; np < 2; np++) {
                uint32_t off = (uint32_t)(((brow + np * 16) * AP + bcol) * 2);
                uint32_t r4[4];
                ldsm4(r4, aBh + off);
                bh[np*2][0] = r4[0]; bh[np*2][1] = r4[1];
                bh[np*2+1][0] = r4[2]; bh[np*2+1][1] = r4[3];
                ldsm4(r4, aBl + off);
                bl[np*2][0] = r4[0]; bl[np*2][1] = r4[1];
                bl[np*2+1][0] = r4[2]; bl[np*2+1][1] = r4[3];
            }
            #pragma unroll
            for (int mt = 0; mt < 4; mt++)
                #pragma unroll
                for (int nt = 0; nt < 4; nt++) {
                    mma16816(acc[mt][nt], ah[mt], bh[nt]);
                    mma16816(acc[mt][nt], ah[mt], bl[nt]);
                    mma16816(acc[mt][nt], al[mt], bh[nt]);
                }
        }
        __syncthreads();
    }

    // epilogue: add bias, scale (Q), split hi/lo, scatter to bf16 scratch
    #pragma unroll
    for (int mt = 0; mt < 4; mt++) {
        int r = m0 + wm * 64 + mt * 16 + (lane >> 2);
        int b = r >> 11;
        int s = r & (SEQ - 1);
        #pragma unroll
        for (int nt = 0; nt < 4; nt++) {
            int o = n0 + wn * 32 + nt * 8 + 2 * (lane & 3);
            int h = o >> 6;
            int d = o & (HDIM - 1);
            size_t p = (((size_t)b * NHEADS + h) * SEQ + s) * HDIM + d;
            float x0 = (acc[mt][nt][0] + bias[o])     * oscale;
            float x1 = (acc[mt][nt][1] + bias[o + 1]) * oscale;
            float x2 = (acc[mt][nt][2] + bias[o])     * oscale;
            float x3 = (acc[mt][nt][3] + bias[o + 1]) * oscale;
            uint32_t h01 = pack_hi(x0, x1), h23 = pack_hi(x2, x3);
            *(uint32_t*)&dstH[p] = h01;
            *(uint32_t*)&dstL[p] = pack_lo(x0, x1, h01);
            *(uint32_t*)&dstH[p + 8 * HDIM] = h23;
            *(uint32_t*)&dstL[p + 8 * HDIM] = pack_lo(x2, x3, h23);
        }
    }
}

// ===========================================================================
// Kernel 2: flash attention, mma.sync bf16 hi/lo, cp.async double-buffered,
// 2 CTAs/SM, base-2 online softmax (Q pre-scaled by log2e/8).
// ===========================================================================
#define KP 72
#define ARRB  (64*KP*2)     // 9216 bytes per array
#define STAGEB (4*ARRB)     // Kh,Kl,Vh,Vl
#define ATTN_SMEM (2*STAGEB)
#define NT (SEQ/64)

__global__ __launch_bounds__(256, 2)
void attn_mma(float* __restrict__ out)
{
    extern __shared__ char smem[];
    const uint32_t sb = smem_u32(smem);

    const int tid  = threadIdx.x;
    const int lane = tid & 31;
    const int wid  = tid >> 5;
    const int q0   = blockIdx.x * 128;
    const int bh   = blockIdx.y;
    const size_t base = (size_t)bh * SEQ * HDIM;

    const int crow = tid >> 3;          // 0..31, +32 per half
    const int cch  = (tid & 7) * 8;     // bf16 col of 16B chunk

    // issue stage 0 loads
    {
        #pragma unroll
        for (int r = 0; r < 8; r++) {
            const __nv_bfloat16* g = (r < 2) ? g_Kh : (r < 4) ? g_Kl
                                   : (r < 6) ? g_Vh : g_Vl;
            int arr = r >> 1;
            int row = (r & 1) * 32 + crow;
            cpa16(sb + arr * ARRB + (uint32_t)((row * KP + cch) * 2),
                  g + base + (size_t)row * HDIM + cch);
        }
        CP_COMMIT();
    }

    // ---- Q fragments (bf16 hi/lo scratch, already scaled) ----
    const int qrow = q0 + wid * 16 + (lane >> 2);
    const int qc   = 2 * (lane & 3);
    uint32_t qh[4][4], ql[4][4];
    #pragma unroll
    for (int kt = 0; kt < 4; kt++) {
        int c = kt * 16 + qc;
        qh[kt][0] = *(const uint32_t*)&g_Qh[base + (size_t)qrow * HDIM + c];
        qh[kt][1] = *(const uint32_t*)&g_Qh[base + (size_t)(qrow + 8) * HDIM + c];
        qh[kt][2] = *(const uint32_t*)&g_Qh[base + (size_t)qrow * HDIM + c + 8];
        qh[kt][3] = *(const uint32_t*)&g_Qh[base + (size_t)(qrow + 8) * HDIM + c + 8];
        ql[kt][0] = *(const uint32_t*)&g_Ql[base + (size_t)qrow * HDIM + c];
        ql[kt][1] = *(const uint32_t*)&g_Ql[base + (size_t)(qrow + 8) * HDIM + c];
        ql[kt][2] = *(const uint32_t*)&g_Ql[base + (size_t)qrow * HDIM + c + 8];
        ql[kt][3] = *(const uint32_t*)&g_Ql[base + (size_t)(qrow + 8) * HDIM + c + 8];
    }

    float m[2] = { -INFINITY, -INFINITY };
    float l[2] = { 0.0f, 0.0f };
    float o[8][4];
    #pragma unroll
    for (int nt = 0; nt < 8; nt++)
        #pragma unroll
        for (int q = 0; q < 4; q++) o[nt][q] = 0.0f;

    for (int t = 0; t < NT; t++) {
        if (t + 1 < NT) {
            const uint32_t st1 = ((t + 1) & 1) * STAGEB;
            const size_t goff = base + (size_t)(t + 1) * 64 * HDIM;
            #pragma unroll
            for (int r = 0; r < 8; r++) {
                const __nv_bfloat16* g = (r < 2) ? g_Kh : (r < 4) ? g_Kl
                                       : (r < 6) ? g_Vh : g_Vl;
                int arr = r >> 1;
                int row = (r & 1) * 32 + crow;
                cpa16(sb + st1 + arr * ARRB + (uint32_t)((row * KP + cch) * 2),
                      g + goff + (size_t)row * HDIM + cch);
            }
            CP_COMMIT();
            CP_WAIT1();
        } else {
            CP_WAIT0();
        }
        __syncthreads();

        const uint32_t stg = (t & 1) * STAGEB;
        const uint32_t aKh = sb + stg;
        const uint32_t aKl = aKh + ARRB;
        const uint32_t aVh = aKl + ARRB;
        const uint32_t aVl = aVh + ARRB;

        // ---- S = Q K^T (base-2 log scale already folded into Q) ----
        float s[8][4];
        #pragma unroll
        for (int nt = 0; nt < 8; nt++)
            #pragma unroll
            for (int q = 0; q < 4; q++) s[nt][q] = 0.0f;

        #pragma unroll
        for (int ks = 0; ks < 4; ks++) {
            const int krow = (lane & 7) + ((lane >> 4) << 3);
            const int kcol = ks * 16 + ((lane >> 3) & 1) * 8;
            #pragma unroll
            for (int np = 0; np < 4; np++) {
                uint32_t off = (uint32_t)(((krow + np * 16) * KP + kcol) * 2);
                uint32_t rh[4], rl[4];
                ldsm4(rh, aKh + off);
                ldsm4(rl, aKl + off);
                uint32_t b0h[2] = { rh[0], rh[1] }, b1h[2] = { rh[2], rh[3] };
                uint32_t b0l[2] = { rl[0], rl[1] }, b1l[2] = { rl[2], rl[3] };
                mma16816(s[np*2],   qh[ks], b0h);
                mma16816(s[np*2],   qh[ks], b0l);
                mma16816(s[np*2],   ql[ks], b0h);
                mma16816(s[np*2+1], qh[ks], b1h);
                mma16816(s[np*2+1], qh[ks], b1l);
                mma16816(s[np*2+1], ql[ks], b1h);
            }
        }

        // ---- online softmax, base 2 ----
        float sc0, sc1;
        {
            float mt = -INFINITY;
            #pragma unroll
            for (int nt = 0; nt < 8; nt++)
                mt = fmaxf(mt, fmaxf(s[nt][0], s[nt][1]));
            mt = fmaxf(mt, __shfl_xor_sync(0xffffffffu, mt, 1));
            mt = fmaxf(mt, __shfl_xor_sync(0xffffffffu, mt, 2));
            float mn = fmaxf(m[0], mt);
            sc0 = exp2f(m[0] - mn);
            m[0] = mn;
            float ps = 0.0f;
            #pragma unroll
            for (int nt = 0; nt < 8; nt++) {
                s[nt][0] = exp2f(s[nt][0] - mn);
                s[nt][1] = exp2f(s[nt][1] - mn);
                ps += s[nt][0] + s[nt][1];
            }
            ps += __shfl_xor_sync(0xffffffffu, ps, 1);
            ps += __shfl_xor_sync(0xffffffffu, ps, 2);
            l[0] = l[0] * sc0 + ps;
        }
        {
            float mt = -INFINITY;
            #pragma unroll
            for (int nt = 0; nt < 8; nt++)
                mt = fmaxf(mt, fmaxf(s[nt][2], s[nt][3]));
            mt = fmaxf(mt, __shfl_xor_sync(0xffffffffu, mt, 1));
            mt = fmaxf(mt, __shfl_xor_sync(0xffffffffu, mt, 2));
            float mn = fmaxf(m[1], mt);
            sc1 = exp2f(m[1] - mn);
            m[1] = mn;
            float ps = 0.0f;
            #pragma unroll
            for (int nt = 0; nt < 8; nt++) {
                s[nt][2] = exp2f(s[nt][2] - mn);
                s[nt][3] = exp2f(s[nt][3] - mn);
                ps += s[nt][2] + s[nt][3];
            }
            ps += __shfl_xor_sync(0xffffffffu, ps, 1);
            ps += __shfl_xor_sync(0xffffffffu, ps, 2);
            l[1] = l[1] * sc1 + ps;
        }
        #pragma unroll
        for (int nt = 0; nt < 8; nt++) {
            o[nt][0] *= sc0; o[nt][1] *= sc0;
            o[nt][2] *= sc1; o[nt][3] *= sc1;
        }

        // ---- P repack (C-frag -> A-frag, registers only) ----
        uint32_t ph[4][4], pl[4][4];
        #pragma unroll
        for (int kp = 0; kp < 4; kp++) {
            const int t0 = 2 * kp, t1 = 2 * kp + 1;
            ph[kp][0] = pack_hi(s[t0][0], s[t0][1]); pl[kp][0] = pack_lo(s[t0][0], s[t0][1], ph[kp][0]);
            ph[kp][1] = pack_hi(s[t0][2], s[t0][3]); pl[kp][1] = pack_lo(s[t0][2], s[t0][3], ph[kp][1]);
            ph[kp][2] = pack_hi(s[t1][0], s[t1][1]); pl[kp][2] = pack_lo(s[t1][0], s[t1][1], ph[kp][2]);
            ph[kp][3] = pack_hi(s[t1][2], s[t1][3]); pl[kp][3] = pack_lo(s[t1][2], s[t1][3], ph[kp][3]);
        }

        // ---- O += P V ----
        #pragma unroll
        for (int kp = 0; kp < 4; kp++) {
            const int vrow = kp * 16 + (lane & 7) + (((lane >> 3) & 1) << 3);
            #pragma unroll
            for (int np = 0; np < 4; np++) {
                const int vcol = np * 16 + ((lane >> 4) << 3);
                uint32_t off = (uint32_t)((vrow * KP + vcol) * 2);
                uint32_t rh[4], rl[4];
                ldsm4t(rh, aVh + off);
                ldsm4t(rl, aVl + off);
                uint32_t b0h[2] = { rh[0], rh[1] }, b1h[2] = { rh[2], rh[3] };
                uint32_t b0l[2] = { rl[0], rl[1] }, b1l[2] = { rl[2], rl[3] };
                mma16816(o[np*2],   ph[kp], b0h);
                mma16816(o[np*2],   ph[kp], b0l);
                mma16816(o[np*2],   pl[kp], b0h);
                mma16816(o[np*2+1], ph[kp], b1h);
                mma16816(o[np*2+1], ph[kp], b1l);
                mma16816(o[np*2+1], pl[kp], b1h);
            }
        }
        __syncthreads();
    }

    // ---- epilogue ----
    const int b = bh >> 4;
    const int h = bh & (NHEADS - 1);
    const float inv0 = 1.0f / l[0];
    const float inv1 = 1.0f / l[1];
    const int r = q0 + wid * 16 + (lane >> 2);
    #pragma unroll
    for (int nt = 0; nt < 8; nt++) {
        int d = nt * 8 + 2 * (lane & 3);
        *(float2*)&out[((size_t)b * SEQ + r) * HID + h * HDIM + d] =
            make_float2(o[nt][0] * inv0, o[nt][1] * inv0);
        *(float2*)&out[((size_t)b * SEQ + r + 8) * HID + h * HDIM + d] =
            make_float2(o[nt][2] * inv1, o[nt][3] * inv1);
    }
}

// ---------------------------------------------------------------------------
extern "C" void kernel_launch(void* const* d_in, const int* in_sizes, int n_in,
                              void* d_out, int out_size)
{
    const float* hidden = (const float*)d_in[0];
    const float* Wq = (const float*)d_in[1];
    const float* bq = (const float*)d_in[2];
    const float* Wk = (const float*)d_in[3];
    const float* bk = (const float*)d_in[4];
    const float* Wv = (const float*)d_in[5];
    const float* bv = (const float*)d_in[6];
    float* out = (float*)d_out;

    qkv_mma<<<dim3(HID / 128, TOKS / 128, 3), 256>>>(hidden, Wq, bq, Wk, bk, Wv, bv);

    cudaFuncSetAttribute(attn_mma, cudaFuncAttributeMaxDynamicSharedMemorySize, ATTN_SMEM);
    attn_mma<<<dim3(SEQ / 128, BATCH * NHEADS), 256, ATTN_SMEM>>>(out);
}

// round 7
// speedup vs baseline: 1.5284x; 1.3763x over previous
#include <cuda_runtime.h>
#include <cuda_fp16.h>
#include <math.h>
#include <stdint.h>

#define HID    1024
#define NHEADS 16
#define HDIM   64
#define SEQ    2048
#define BATCH  2
#define TOKS   (BATCH*SEQ)   // 4096
#define NELEM  (BATCH*NHEADS*SEQ*HDIM)

// fp16 scratch, [B, NH, S, HD]. Q hi/lo pre-scaled by log2(e)/sqrt(HD); K,V single.
__device__ __align__(16) __half g_Qh[NELEM], g_Ql[NELEM];
__device__ __align__(16) __half g_Kf[NELEM], g_Vf[NELEM];

// ===================== helpers =====================
__device__ __forceinline__ uint32_t smem_u32(const void* p) {
    uint32_t a;
    asm("{ .reg .u64 t; cvta.to.shared.u64 t, %1; cvt.u32.u64 %0, t; }"
        : "=r"(a) : "l"(p));
    return a;
}
__device__ __forceinline__ void ldsm4(uint32_t* r, uint32_t a) {
    asm volatile("ldmatrix.sync.aligned.m8n8.x4.shared.b16 {%0,%1,%2,%3}, [%4];"
        : "=r"(r[0]), "=r"(r[1]), "=r"(r[2]), "=r"(r[3]) : "r"(a));
}
__device__ __forceinline__ void ldsm4t(uint32_t* r, uint32_t a) {
    asm volatile("ldmatrix.sync.aligned.m8n8.x4.trans.shared.b16 {%0,%1,%2,%3}, [%4];"
        : "=r"(r[0]), "=r"(r[1]), "=r"(r[2]), "=r"(r[3]) : "r"(a));
}
// D += A * B   (m16n8k16, fp16 in, fp32 accumulate)
__device__ __forceinline__ void mmaf16(float* d, const uint32_t* a, const uint32_t* b) {
    asm volatile(
        "mma.sync.aligned.m16n8k16.row.col.f32.f16.f16.f32 "
        "{%0,%1,%2,%3}, {%4,%5,%6,%7}, {%8,%9}, {%0,%1,%2,%3};"
        : "+f"(d[0]), "+f"(d[1]), "+f"(d[2]), "+f"(d[3])
        : "r"(a[0]), "r"(a[1]), "r"(a[2]), "r"(a[3]), "r"(b[0]), "r"(b[1]));
}
__device__ __forceinline__ uint32_t pack_h(float x, float y) {
    __half2 h = __floats2half2_rn(x, y);
    return *reinterpret_cast<uint32_t*>(&h);
}
__device__ __forceinline__ uint32_t pack_hlo(float x, float y, uint32_t hi) {
    __half2 h = *reinterpret_cast<__half2*>(&hi);
    return pack_h(x - __half2float(h.x), y - __half2float(h.y));
}
__device__ __forceinline__ void cpa16(uint32_t s, const void* g) {
    asm volatile("{\n\t.reg .u64 gp;\n\tcvta.to.global.u64 gp, %1;\n\t"
                 "cp.async.cg.shared.global [%0], [gp], 16;\n\t}"
                 :: "r"(s), "l"(g) : "memory");
}
#define CP_COMMIT() asm volatile("cp.async.commit_group;" ::: "memory")
#define CP_WAIT1()  asm volatile("cp.async.wait_group 1;" ::: "memory")
#define CP_WAIT0()  asm volatile("cp.async.wait_group 0;" ::: "memory")

// ===========================================================================
// Kernel 1: QKV projection, mma.sync fp16 both-split (hh+hl+lh).
// CTA 128x128, BK=32, 8 warps, 2 CTAs/SM.
// Epilogue: z=0 -> Q hi/lo fp16 (scaled by 0.125*log2e); z=1,2 -> K,V single.
// ===========================================================================
#define AP 40

__global__ __launch_bounds__(256, 2)
void qkv_mma(const float* __restrict__ hidden,
             const float* __restrict__ Wq, const float* __restrict__ bq,
             const float* __restrict__ Wk, const float* __restrict__ bk,
             const float* __restrict__ Wv, const float* __restrict__ bv)
{
    __shared__ __half sAh[128*AP], sAl[128*AP];
    __shared__ __half sBh[128*AP], sBl[128*AP];

    const int z = blockIdx.z;
    const float* W    = (z == 0) ? Wq : ((z == 1) ? Wk : Wv);
    const float* bias = (z == 0) ? bq : ((z == 1) ? bk : bv);
    const float oscale = (z == 0) ? 0.125f * 1.4426950408889634f : 1.0f;

    const int tid  = threadIdx.x;
    const int lane = tid & 31;
    const int wid  = tid >> 5;
    const int wm   = wid >> 2;
    const int wn   = wid & 3;
    const int m0   = blockIdx.y * 128;
    const int n0   = blockIdx.x * 128;

    const uint32_t aAh = smem_u32(sAh), aAl = smem_u32(sAl);
    const uint32_t aBh = smem_u32(sBh), aBl = smem_u32(sBl);

    float acc[4][4][4];
    #pragma unroll
    for (int mt = 0; mt < 4; mt++)
        #pragma unroll
        for (int nt = 0; nt < 4; nt++)
            #pragma unroll
            for (int q = 0; q < 4; q++) acc[mt][nt][q] = 0.0f;

    for (int kt = 0; kt < HID; kt += 32) {
        #pragma unroll
        for (int r = 0; r < 4; r++) {
            int idx = tid + r * 256;
            int row = idx >> 3;
            int c   = (idx & 7) * 4;
            float4 a = *(const float4*)&hidden[(size_t)(m0 + row) * HID + kt + c];
            uint32_t h0 = pack_h(a.x, a.y), h1 = pack_h(a.z, a.w);
            *(uint2*)&sAh[row * AP + c] = make_uint2(h0, h1);
            *(uint2*)&sAl[row * AP + c] =
                make_uint2(pack_hlo(a.x, a.y, h0), pack_hlo(a.z, a.w, h1));
            float4 w = *(const float4*)&W[(size_t)(n0 + row) * HID + kt + c];
            uint32_t g0 = pack_h(w.x, w.y), g1 = pack_h(w.z, w.w);
            *(uint2*)&sBh[row * AP + c] = make_uint2(g0, g1);
            *(uint2*)&sBl[row * AP + c] =
                make_uint2(pack_hlo(w.x, w.y, g0), pack_hlo(w.z, w.w, g1));
        }
        __syncthreads();

        #pragma unroll
        for (int ks = 0; ks < 2; ks++) {
            uint32_t ah[4][4], al[4][4], bh[4][2], bl[4][2];
            const int arow = wm * 64 + (lane & 15);
            const int acol = ks * 16 + ((lane >> 4) << 3);
            #pragma unroll
            for (int mt = 0; mt < 4; mt++) {
                uint32_t off = (uint32_t)(((arow + mt * 16) * AP + acol) * 2);
                ldsm4(ah[mt], aAh + off);
                ldsm4(al[mt], aAl + off);
            }
            const int brow = wn * 32 + (lane & 7) + ((lane >> 4) << 3);
            const int bcol = ks * 16 + ((lane >> 3) & 1) * 8;
            #pragma unroll
            for (int np = 0; np < 2; np++) {
                uint32_t off = (uint32_t)(((brow + np * 16) * AP + bcol) * 2);
                uint32_t r4[4];
                ldsm4(r4, aBh + off);
                bh[np*2][0] = r4[0]; bh[np*2][1] = r4[1];
                bh[np*2+1][0] = r4[2]; bh[np*2+1][1] = r4[3];
                ldsm4(r4, aBl + off);
                bl[np*2][0] = r4[0]; bl[np*2][1] = r4[1];
                bl[np*2+1][0] = r4[2]; bl[np*2+1][1] = r4[3];
            }
            #pragma unroll
            for (int mt = 0; mt < 4; mt++)
                #pragma unroll
                for (int nt = 0; nt < 4; nt++) {
                    mmaf16(acc[mt][nt], ah[mt], bh[nt]);
                    mmaf16(acc[mt][nt], ah[mt], bl[nt]);
                    mmaf16(acc[mt][nt], al[mt], bh[nt]);
                }
        }
        __syncthreads();
    }

    // epilogue
    #pragma unroll
    for (int mt = 0; mt < 4; mt++) {
        int r = m0 + wm * 64 + mt * 16 + (lane >> 2);
        int b = r >> 11;
        int s = r & (SEQ - 1);
        #pragma unroll
        for (int nt = 0; nt < 4; nt++) {
            int o = n0 + wn * 32 + nt * 8 + 2 * (lane & 3);
            int h = o >> 6;
            int d = o & (HDIM - 1);
            size_t p = (((size_t)b * NHEADS + h) * SEQ + s) * HDIM + d;
            float x0 = (acc[mt][nt][0] + bias[o])     * oscale;
            float x1 = (acc[mt][nt][1] + bias[o + 1]) * oscale;
            float x2 = (acc[mt][nt][2] + bias[o])     * oscale;
            float x3 = (acc[mt][nt][3] + bias[o + 1]) * oscale;
            uint32_t h01 = pack_h(x0, x1), h23 = pack_h(x2, x3);
            if (z == 0) {
                *(uint32_t*)&g_Qh[p] = h01;
                *(uint32_t*)&g_Ql[p] = pack_hlo(x0, x1, h01);
                *(uint32_t*)&g_Qh[p + 8 * HDIM] = h23;
                *(uint32_t*)&g_Ql[p + 8 * HDIM] = pack_hlo(x2, x3, h23);
            } else {
                __half* dstF = (z == 1) ? g_Kf : g_Vf;
                *(uint32_t*)&dstF[p] = h01;
                *(uint32_t*)&dstF[p + 8 * HDIM] = h23;
            }
        }
    }
}

// ===========================================================================
// Kernel 2: flash attention fp16: QK = 2 MMAs (Q hi/lo, K single),
// PV = 1 MMA (P single, V single). cp.async double-buffered, 2 CTAs/SM,
// base-2 online softmax.
// ===========================================================================
#define KP 72
#define ARRB  (64*KP*2)       // 9216 bytes per array (fp16)
#define STAGEB (2*ARRB)       // Kf, Vf
#define ATTN_SMEM (2*STAGEB)  // 36864
#define NT (SEQ/64)

__global__ __launch_bounds__(256, 2)
void attn_mma(float* __restrict__ out)
{
    extern __shared__ char smem[];
    const uint32_t sb = smem_u32(smem);

    const int tid  = threadIdx.x;
    const int lane = tid & 31;
    const int wid  = tid >> 5;
    const int q0   = blockIdx.x * 128;
    const int bh   = blockIdx.y;
    const size_t base = (size_t)bh * SEQ * HDIM;

    const int crow = tid >> 3;          // 0..31 (+32 for second half)
    const int cch  = (tid & 7) * 8;     // fp16 col of 16B chunk

    // issue stage 0 loads (K, V single arrays)
    {
        #pragma unroll
        for (int r = 0; r < 4; r++) {
            const __half* g = (r < 2) ? g_Kf : g_Vf;
            int arr = r >> 1;
            int row = (r & 1) * 32 + crow;
            cpa16(sb + arr * ARRB + (uint32_t)((row * KP + cch) * 2),
                  g + base + (size_t)row * HDIM + cch);
        }
        CP_COMMIT();
    }

    // ---- Q fragments (fp16 hi/lo scratch, already scaled) ----
    const int qrow = q0 + wid * 16 + (lane >> 2);
    const int qc   = 2 * (lane & 3);
    uint32_t qh[4][4], ql[4][4];
    #pragma unroll
    for (int kt = 0; kt < 4; kt++) {
        int c = kt * 16 + qc;
        qh[kt][0] = *(const uint32_t*)&g_Qh[base + (size_t)qrow * HDIM + c];
        qh[kt][1] = *(const uint32_t*)&g_Qh[base + (size_t)(qrow + 8) * HDIM + c];
        qh[kt][2] = *(const uint32_t*)&g_Qh[base + (size_t)qrow * HDIM + c + 8];
        qh[kt][3] = *(const uint32_t*)&g_Qh[base + (size_t)(qrow + 8) * HDIM + c + 8];
        ql[kt][0] = *(const uint32_t*)&g_Ql[base + (size_t)qrow * HDIM + c];
        ql[kt][1] = *(const uint32_t*)&g_Ql[base + (size_t)(qrow + 8) * HDIM + c];
        ql[kt][2] = *(const uint32_t*)&g_Ql[base + (size_t)qrow * HDIM + c + 8];
        ql[kt][3] = *(const uint32_t*)&g_Ql[base + (size_t)(qrow + 8) * HDIM + c + 8];
    }

    float m[2] = { -INFINITY, -INFINITY };
    float l[2] = { 0.0f, 0.0f };
    float o[8][4];
    #pragma unroll
    for (int nt = 0; nt < 8; nt++)
        #pragma unroll
        for (int q = 0; q < 4; q++) o[nt][q] = 0.0f;

    for (int t = 0; t < NT; t++) {
        if (t + 1 < NT) {
            const uint32_t st1 = ((t + 1) & 1) * STAGEB;
            const size_t goff = base + (size_t)(t + 1) * 64 * HDIM;
            #pragma unroll
            for (int r = 0; r < 4; r++) {
                const __half* g = (r < 2) ? g_Kf : g_Vf;
                int arr = r >> 1;
                int row = (r & 1) * 32 + crow;
                cpa16(sb + st1 + arr * ARRB + (uint32_t)((row * KP + cch) * 2),
                      g + goff + (size_t)row * HDIM + cch);
            }
            CP_COMMIT();
            CP_WAIT1();
        } else {
            CP_WAIT0();
        }
        __syncthreads();

        const uint32_t stg = (t & 1) * STAGEB;
        const uint32_t aK = sb + stg;
        const uint32_t aV = aK + ARRB;

        // ---- S = Q K^T (2 MMAs: qh + ql vs single K) ----
        float s[8][4];
        #pragma unroll
        for (int nt = 0; nt < 8; nt++)
            #pragma unroll
            for (int q = 0; q < 4; q++) s[nt][q] = 0.0f;

        #pragma unroll
        for (int ks = 0; ks < 4; ks++) {
            const int krow = (lane & 7) + ((lane >> 4) << 3);
            const int kcol = ks * 16 + ((lane >> 3) & 1) * 8;
            #pragma unroll
            for (int np = 0; np < 4; np++) {
                uint32_t off = (uint32_t)(((krow + np * 16) * KP + kcol) * 2);
                uint32_t rk[4];
                ldsm4(rk, aK + off);
                uint32_t b0[2] = { rk[0], rk[1] }, b1[2] = { rk[2], rk[3] };
                mmaf16(s[np*2],   qh[ks], b0);
                mmaf16(s[np*2],   ql[ks], b0);
                mmaf16(s[np*2+1], qh[ks], b1);
                mmaf16(s[np*2+1], ql[ks], b1);
            }
        }

        // ---- online softmax, base 2 ----
        float sc0, sc1;
        {
            float mt = -INFINITY;
            #pragma unroll
            for (int nt = 0; nt < 8; nt++)
                mt = fmaxf(mt, fmaxf(s[nt][0], s[nt][1]));
            mt = fmaxf(mt, __shfl_xor_sync(0xffffffffu, mt, 1));
            mt = fmaxf(mt, __shfl_xor_sync(0xffffffffu, mt, 2));
            float mn = fmaxf(m[0], mt);
            sc0 = exp2f(m[0] - mn);
            m[0] = mn;
            float ps = 0.0f;
            #pragma unroll
            for (int nt = 0; nt < 8; nt++) {
                s[nt][0] = exp2f(s[nt][0] - mn);
                s[nt][1] = exp2f(s[nt][1] - mn);
                ps += s[nt][0] + s[nt][1];
            }
            ps += __shfl_xor_sync(0xffffffffu, ps, 1);
            ps += __shfl_xor_sync(0xffffffffu, ps, 2);
            l[0] = l[0] * sc0 + ps;
        }
        {
            float mt = -INFINITY;
            #pragma unroll
            for (int nt = 0; nt < 8; nt++)
                mt = fmaxf(mt, fmaxf(s[nt][2], s[nt][3]));
            mt = fmaxf(mt, __shfl_xor_sync(0xffffffffu, mt, 1));
            mt = fmaxf(mt, __shfl_xor_sync(0xffffffffu, mt, 2));
            float mn = fmaxf(m[1], mt);
            sc1 = exp2f(m[1] - mn);
            m[1] = mn;
            float ps = 0.0f;
            #pragma unroll
            for (int nt = 0; nt < 8; nt++) {
                s[nt][2] = exp2f(s[nt][2] - mn);
                s[nt][3] = exp2f(s[nt][3] - mn);
                ps += s[nt][2] + s[nt][3];
            }
            ps += __shfl_xor_sync(0xffffffffu, ps, 1);
            ps += __shfl_xor_sync(0xffffffffu, ps, 2);
            l[1] = l[1] * sc1 + ps;
        }
        #pragma unroll
        for (int nt = 0; nt < 8; nt++) {
            o[nt][0] *= sc0; o[nt][1] *= sc0;
            o[nt][2] *= sc1; o[nt][3] *= sc1;
        }

        // ---- P repack: single fp16 A-fragments ----
        uint32_t ph[4][4];
        #pragma unroll
        for (int kp = 0; kp < 4; kp++) {
            const int t0 = 2 * kp, t1 = 2 * kp + 1;
            ph[kp][0] = pack_h(s[t0][0], s[t0][1]);
            ph[kp][1] = pack_h(s[t0][2], s[t0][3]);
            ph[kp][2] = pack_h(s[t1][0], s[t1][1]);
            ph[kp][3] = pack_h(s[t1][2], s[t1][3]);
        }

        // ---- O += P V (1 MMA per subtile) ----
        #pragma unroll
        for (int kp = 0; kp < 4; kp++) {
            const int vrow = kp * 16 + (lane & 7) + (((lane >> 3) & 1) << 3);
            #pragma unroll
            for (int np = 0; np < 4; np++) {
                const int vcol = np * 16 + ((lane >> 4) << 3);
                uint32_t off = (uint32_t)((vrow * KP + vcol) * 2);
                uint32_t rv[4];
                ldsm4t(rv, aV + off);
                uint32_t b0[2] = { rv[0], rv[1] }, b1[2] = { rv[2], rv[3] };
                mmaf16(o[np*2],   ph[kp], b0);
                mmaf16(o[np*2+1], ph[kp], b1);
            }
        }
        __syncthreads();
    }

    // ---- epilogue ----
    const int b = bh >> 4;
    const int h = bh & (NHEADS - 1);
    const float inv0 = 1.0f / l[0];
    const float inv1 = 1.0f / l[1];
    const int r = q0 + wid * 16 + (lane >> 2);
    #pragma unroll
    for (int nt = 0; nt < 8; nt++) {
        int d = nt * 8 + 2 * (lane & 3);
        *(float2*)&out[((size_t)b * SEQ + r) * HID + h * HDIM + d] =
            make_float2(o[nt][0] * inv0, o[nt][1] * inv0);
        *(float2*)&out[((size_t)b * SEQ + r + 8) * HID + h * HDIM + d] =
            make_float2(o[nt][2] * inv1, o[nt][3] * inv1);
    }
}

// ---------------------------------------------------------------------------
extern "C" void kernel_launch(void* const* d_in, const int* in_sizes, int n_in,
                              void* d_out, int out_size)
{
    const float* hidden = (const float*)d_in[0];
    const float* Wq = (const float*)d_in[1];
    const float* bq = (const float*)d_in[2];
    const float* Wk = (const float*)d_in[3];
    const float* bk = (const float*)d_in[4];
    const float* Wv = (const float*)d_in[5];
    const float* bv = (const float*)d_in[6];
    float* out = (float*)d_out;

    qkv_mma<<<dim3(HID / 128, TOKS / 128, 3), 256>>>(hidden, Wq, bq, Wk, bk, Wv, bv);

    cudaFuncSetAttribute(attn_mma, cudaFuncAttributeMaxDynamicSharedMemorySize, ATTN_SMEM);
    attn_mma<<<dim3(SEQ / 128, BATCH * NHEADS), 256, ATTN_SMEM>>>(out);
}

// round 8
// speedup vs baseline: 2.0194x; 1.3213x over previous
#include <cuda_runtime.h>
#include <cuda_fp16.h>
#include <math.h>
#include <stdint.h>

#define HID    1024
#define NHEADS 16
#define HDIM   64
#define SEQ    2048
#define BATCH  2
#define TOKS   (BATCH*SEQ)   // 4096
#define NELEM  (BATCH*NHEADS*SEQ*HDIM)

// fp16 scratch, [B, NH, S, HD]. Q pre-scaled by log2(e)/sqrt(HD). All single.
__device__ __align__(16) __half g_Qf[NELEM], g_Kf[NELEM], g_Vf[NELEM];

// ===================== helpers =====================
__device__ __forceinline__ uint32_t smem_u32(const void* p) {
    uint32_t a;
    asm("{ .reg .u64 t; cvta.to.shared.u64 t, %1; cvt.u32.u64 %0, t; }"
        : "=r"(a) : "l"(p));
    return a;
}
__device__ __forceinline__ void ldsm4(uint32_t* r, uint32_t a) {
    asm volatile("ldmatrix.sync.aligned.m8n8.x4.shared.b16 {%0,%1,%2,%3}, [%4];"
        : "=r"(r[0]), "=r"(r[1]), "=r"(r[2]), "=r"(r[3]) : "r"(a));
}
__device__ __forceinline__ void ldsm4t(uint32_t* r, uint32_t a) {
    asm volatile("ldmatrix.sync.aligned.m8n8.x4.trans.shared.b16 {%0,%1,%2,%3}, [%4];"
        : "=r"(r[0]), "=r"(r[1]), "=r"(r[2]), "=r"(r[3]) : "r"(a));
}
__device__ __forceinline__ void mmaf16(float* d, const uint32_t* a, const uint32_t* b) {
    asm volatile(
        "mma.sync.aligned.m16n8k16.row.col.f32.f16.f16.f32 "
        "{%0,%1,%2,%3}, {%4,%5,%6,%7}, {%8,%9}, {%0,%1,%2,%3};"
        : "+f"(d[0]), "+f"(d[1]), "+f"(d[2]), "+f"(d[3])
        : "r"(a[0]), "r"(a[1]), "r"(a[2]), "r"(a[3]), "r"(b[0]), "r"(b[1]));
}
__device__ __forceinline__ uint32_t pack_h(float x, float y) {
    __half2 h = __floats2half2_rn(x, y);
    return *reinterpret_cast<uint32_t*>(&h);
}
__device__ __forceinline__ uint32_t pack_hlo(float x, float y, uint32_t hi) {
    __half2 h = *reinterpret_cast<__half2*>(&hi);
    return pack_h(x - __half2float(h.x), y - __half2float(h.y));
}
__device__ __forceinline__ void cpa16(uint32_t s, const void* g) {
    asm volatile("{\n\t.reg .u64 gp;\n\tcvta.to.global.u64 gp, %1;\n\t"
                 "cp.async.cg.shared.global [%0], [gp], 16;\n\t}"
                 :: "r"(s), "l"(g) : "memory");
}
#define CP_COMMIT() asm volatile("cp.async.commit_group;" ::: "memory")
#define CP_WAIT1()  asm volatile("cp.async.wait_group 1;" ::: "memory")
#define CP_WAIT0()  asm volatile("cp.async.wait_group 0;" ::: "memory")

// ===========================================================================
// Kernel 1: QKV projection, fp16, 2 MMAs: A (hidden) hi/lo split, W single.
// CTA 128x128, BK=32, 8 warps, 2 CTAs/SM.
// Epilogue: single fp16 scratch (Q scaled by 0.125*log2e).
// ===========================================================================
#define AP 40

__global__ __launch_bounds__(256, 2)
void qkv_mma(const float* __restrict__ hidden,
             const float* __restrict__ Wq, const float* __restrict__ bq,
             const float* __restrict__ Wk, const float* __restrict__ bk,
             const float* __restrict__ Wv, const float* __restrict__ bv)
{
    __shared__ __half sAh[128*AP], sAl[128*AP];
    __shared__ __half sB[128*AP];

    const int z = blockIdx.z;
    const float* W    = (z == 0) ? Wq : ((z == 1) ? Wk : Wv);
    const float* bias = (z == 0) ? bq : ((z == 1) ? bk : bv);
    __half* dst       = (z == 0) ? g_Qf : ((z == 1) ? g_Kf : g_Vf);
    const float oscale = (z == 0) ? 0.125f * 1.4426950408889634f : 1.0f;

    const int tid  = threadIdx.x;
    const int lane = tid & 31;
    const int wid  = tid >> 5;
    const int wm   = wid >> 2;
    const int wn   = wid & 3;
    const int m0   = blockIdx.y * 128;
    const int n0   = blockIdx.x * 128;

    const uint32_t aAh = smem_u32(sAh), aAl = smem_u32(sAl);
    const uint32_t aB  = smem_u32(sB);

    float acc[4][4][4];
    #pragma unroll
    for (int mt = 0; mt < 4; mt++)
        #pragma unroll
        for (int nt = 0; nt < 4; nt++)
            #pragma unroll
            for (int q = 0; q < 4; q++) acc[mt][nt][q] = 0.0f;

    for (int kt = 0; kt < HID; kt += 32) {
        #pragma unroll
        for (int r = 0; r < 4; r++) {
            int idx = tid + r * 256;
            int row = idx >> 3;
            int c   = (idx & 7) * 4;
            float4 a = *(const float4*)&hidden[(size_t)(m0 + row) * HID + kt + c];
            uint32_t h0 = pack_h(a.x, a.y), h1 = pack_h(a.z, a.w);
            *(uint2*)&sAh[row * AP + c] = make_uint2(h0, h1);
            *(uint2*)&sAl[row * AP + c] =
                make_uint2(pack_hlo(a.x, a.y, h0), pack_hlo(a.z, a.w, h1));
            float4 w = *(const float4*)&W[(size_t)(n0 + row) * HID + kt + c];
            *(uint2*)&sB[row * AP + c] =
                make_uint2(pack_h(w.x, w.y), pack_h(w.z, w.w));
        }
        __syncthreads();

        #pragma unroll
        for (int ks = 0; ks < 2; ks++) {
            uint32_t ah[4][4], al[4][4], bf[4][2];
            const int arow = wm * 64 + (lane & 15);
            const int acol = ks * 16 + ((lane >> 4) << 3);
            #pragma unroll
            for (int mt = 0; mt < 4; mt++) {
                uint32_t off = (uint32_t)(((arow + mt * 16) * AP + acol) * 2);
                ldsm4(ah[mt], aAh + off);
                ldsm4(al[mt], aAl + off);
            }
            const int brow = wn * 32 + (lane & 7) + ((lane >> 4) << 3);
            const int bcol = ks * 16 + ((lane >> 3) & 1) * 8;
            #pragma unroll
            for (int np = 0; np < 2; np++) {
                uint32_t off = (uint32_t)(((brow + np * 16) * AP + bcol) * 2);
                uint32_t r4[4];
                ldsm4(r4, aB + off);
                bf[np*2][0] = r4[0]; bf[np*2][1] = r4[1];
                bf[np*2+1][0] = r4[2]; bf[np*2+1][1] = r4[3];
            }
            #pragma unroll
            for (int mt = 0; mt < 4; mt++)
                #pragma unroll
                for (int nt = 0; nt < 4; nt++) {
                    mmaf16(acc[mt][nt], ah[mt], bf[nt]);
                    mmaf16(acc[mt][nt], al[mt], bf[nt]);
                }
        }
        __syncthreads();
    }

    // epilogue: add bias, scale (Q), round to fp16, scatter
    #pragma unroll
    for (int mt = 0; mt < 4; mt++) {
        int r = m0 + wm * 64 + mt * 16 + (lane >> 2);
        int b = r >> 11;
        int s = r & (SEQ - 1);
        #pragma unroll
        for (int nt = 0; nt < 4; nt++) {
            int o = n0 + wn * 32 + nt * 8 + 2 * (lane & 3);
            int h = o >> 6;
            int d = o & (HDIM - 1);
            size_t p = (((size_t)b * NHEADS + h) * SEQ + s) * HDIM + d;
            float x0 = (acc[mt][nt][0] + bias[o])     * oscale;
            float x1 = (acc[mt][nt][1] + bias[o + 1]) * oscale;
            float x2 = (acc[mt][nt][2] + bias[o])     * oscale;
            float x3 = (acc[mt][nt][3] + bias[o + 1]) * oscale;
            *(uint32_t*)&dst[p] = pack_h(x0, x1);
            *(uint32_t*)&dst[p + 8 * HDIM] = pack_h(x2, x3);
        }
    }
}

// ===========================================================================
// Kernel 2: flash attention fp16, 1 MMA per subtile for both QK and PV.
// cp.async double-buffered, 2 CTAs/SM, base-2 online softmax.
// ===========================================================================
#define KP 72
#define ARRB  (64*KP*2)       // 9216 bytes per array (fp16)
#define STAGEB (2*ARRB)       // Kf, Vf
#define ATTN_SMEM (2*STAGEB)  // 36864
#define NT (SEQ/64)

__global__ __launch_bounds__(256, 2)
void attn_mma(float* __restrict__ out)
{
    extern __shared__ char smem[];
    const uint32_t sb = smem_u32(smem);

    const int tid  = threadIdx.x;
    const int lane = tid & 31;
    const int wid  = tid >> 5;
    const int q0   = blockIdx.x * 128;
    const int bh   = blockIdx.y;
    const size_t base = (size_t)bh * SEQ * HDIM;

    const int crow = tid >> 3;          // 0..31 (+32 for second half)
    const int cch  = (tid & 7) * 8;     // fp16 col of 16B chunk

    // issue stage 0 loads
    {
        #pragma unroll
        for (int r = 0; r < 4; r++) {
            const __half* g = (r < 2) ? g_Kf : g_Vf;
            int arr = r >> 1;
            int row = (r & 1) * 32 + crow;
            cpa16(sb + arr * ARRB + (uint32_t)((row * KP + cch) * 2),
                  g + base + (size_t)row * HDIM + cch);
        }
        CP_COMMIT();
    }

    // ---- Q fragments (single fp16 scratch, already scaled) ----
    const int qrow = q0 + wid * 16 + (lane >> 2);
    const int qc   = 2 * (lane & 3);
    uint32_t qf[4][4];
    #pragma unroll
    for (int kt = 0; kt < 4; kt++) {
        int c = kt * 16 + qc;
        qf[kt][0] = *(const uint32_t*)&g_Qf[base + (size_t)qrow * HDIM + c];
        qf[kt][1] = *(const uint32_t*)&g_Qf[base + (size_t)(qrow + 8) * HDIM + c];
        qf[kt][2] = *(const uint32_t*)&g_Qf[base + (size_t)qrow * HDIM + c + 8];
        qf[kt][3] = *(const uint32_t*)&g_Qf[base + (size_t)(qrow + 8) * HDIM + c + 8];
    }

    float m[2] = { -INFINITY, -INFINITY };
    float l[2] = { 0.0f, 0.0f };
    float o[8][4];
    #pragma unroll
    for (int nt = 0; nt < 8; nt++)
        #pragma unroll
        for (int q = 0; q < 4; q++) o[nt][q] = 0.0f;

    for (int t = 0; t < NT; t++) {
        if (t + 1 < NT) {
            const uint32_t st1 = ((t + 1) & 1) * STAGEB;
            const size_t goff = base + (size_t)(t + 1) * 64 * HDIM;
            #pragma unroll
            for (int r = 0; r < 4; r++) {
                const __half* g = (r < 2) ? g_Kf : g_Vf;
                int arr = r >> 1;
                int row = (r & 1) * 32 + crow;
                cpa16(sb + st1 + arr * ARRB + (uint32_t)((row * KP + cch) * 2),
                      g + goff + (size_t)row * HDIM + cch);
            }
            CP_COMMIT();
            CP_WAIT1();
        } else {
            CP_WAIT0();
        }
        __syncthreads();

        const uint32_t stg = (t & 1) * STAGEB;
        const uint32_t aK = sb + stg;
        const uint32_t aV = aK + ARRB;

        // ---- S = Q K^T (1 MMA per subtile) ----
        float s[8][4];
        #pragma unroll
        for (int nt = 0; nt < 8; nt++)
            #pragma unroll
            for (int q = 0; q < 4; q++) s[nt][q] = 0.0f;

        #pragma unroll
        for (int ks = 0; ks < 4; ks++) {
            const int krow = (lane & 7) + ((lane >> 4) << 3);
            const int kcol = ks * 16 + ((lane >> 3) & 1) * 8;
            #pragma unroll
            for (int np = 0; np < 4; np++) {
                uint32_t off = (uint32_t)(((krow + np * 16) * KP + kcol) * 2);
                uint32_t rk[4];
                ldsm4(rk, aK + off);
                uint32_t b0[2] = { rk[0], rk[1] }, b1[2] = { rk[2], rk[3] };
                mmaf16(s[np*2],   qf[ks], b0);
                mmaf16(s[np*2+1], qf[ks], b1);
            }
        }

        // ---- online softmax, base 2 ----
        float sc0, sc1;
        {
            float mt = -INFINITY;
            #pragma unroll
            for (int nt = 0; nt < 8; nt++)
                mt = fmaxf(mt, fmaxf(s[nt][0], s[nt][1]));
            mt = fmaxf(mt, __shfl_xor_sync(0xffffffffu, mt, 1));
            mt = fmaxf(mt, __shfl_xor_sync(0xffffffffu, mt, 2));
            float mn = fmaxf(m[0], mt);
            sc0 = exp2f(m[0] - mn);
            m[0] = mn;
            float ps = 0.0f;
            #pragma unroll
            for (int nt = 0; nt < 8; nt++) {
                s[nt][0] = exp2f(s[nt][0] - mn);
                s[nt][1] = exp2f(s[nt][1] - mn);
                ps += s[nt][0] + s[nt][1];
            }
            ps += __shfl_xor_sync(0xffffffffu, ps, 1);
            ps += __shfl_xor_sync(0xffffffffu, ps, 2);
            l[0] = l[0] * sc0 + ps;
        }
        {
            float mt = -INFINITY;
            #pragma unroll
            for (int nt = 0; nt < 8; nt++)
                mt = fmaxf(mt, fmaxf(s[nt][2], s[nt][3]));
            mt = fmaxf(mt, __shfl_xor_sync(0xffffffffu, mt, 1));
            mt = fmaxf(mt, __shfl_xor_sync(0xffffffffu, mt, 2));
            float mn = fmaxf(m[1], mt);
            sc1 = exp2f(m[1] - mn);
            m[1] = mn;
            float ps = 0.0f;
            #pragma unroll
            for (int nt = 0; nt < 8; nt++) {
                s[nt][2] = exp2f(s[nt][2] - mn);
                s[nt][3] = exp2f(s[nt][3] - mn);
                ps += s[nt][2] + s[nt][3];
            }
            ps += __shfl_xor_sync(0xffffffffu, ps, 1);
            ps += __shfl_xor_sync(0xffffffffu, ps, 2);
            l[1] = l[1] * sc1 + ps;
        }
        #pragma unroll
        for (int nt = 0; nt < 8; nt++) {
            o[nt][0] *= sc0; o[nt][1] *= sc0;
            o[nt][2] *= sc1; o[nt][3] *= sc1;
        }

        // ---- P repack: single fp16 A-fragments ----
        uint32_t ph[4][4];
        #pragma unroll
        for (int kp = 0; kp < 4; kp++) {
            const int t0 = 2 * kp, t1 = 2 * kp + 1;
            ph[kp][0] = pack_h(s[t0][0], s[t0][1]);
            ph[kp][1] = pack_h(s[t0][2], s[t0][3]);
            ph[kp][2] = pack_h(s[t1][0], s[t1][1]);
            ph[kp][3] = pack_h(s[t1][2], s[t1][3]);
        }

        // ---- O += P V (1 MMA per subtile) ----
        #pragma unroll
        for (int kp = 0; kp < 4; kp++) {
            const int vrow = kp * 16 + (lane & 7) + (((lane >> 3) & 1) << 3);
            #pragma unroll
            for (int np = 0; np < 4; np++) {
                const int vcol = np * 16 + ((lane >> 4) << 3);
                uint32_t off = (uint32_t)((vrow * KP + vcol) * 2);
                uint32_t rv[4];
                ldsm4t(rv, aV + off);
                uint32_t b0[2] = { rv[0], rv[1] }, b1[2] = { rv[2], rv[3] };
                mmaf16(o[np*2],   ph[kp], b0);
                mmaf16(o[np*2+1], ph[kp], b1);
            }
        }
        __syncthreads();
    }

    // ---- epilogue ----
    const int b = bh >> 4;
    const int h = bh & (NHEADS - 1);
    const float inv0 = 1.0f / l[0];
    const float inv1 = 1.0f / l[1];
    const int r = q0 + wid * 16 + (lane >> 2);
    #pragma unroll
    for (int nt = 0; nt < 8; nt++) {
        int d = nt * 8 + 2 * (lane & 3);
        *(float2*)&out[((size_t)b * SEQ + r) * HID + h * HDIM + d] =
            make_float2(o[nt][0] * inv0, o[nt][1] * inv0);
        *(float2*)&out[((size_t)b * SEQ + r + 8) * HID + h * HDIM + d] =
            make_float2(o[nt][2] * inv1, o[nt][3] * inv1);
    }
}

// ---------------------------------------------------------------------------
extern "C" void kernel_launch(void* const* d_in, const int* in_sizes, int n_in,
                              void* d_out, int out_size)
{
    const float* hidden = (const float*)d_in[0];
    const float* Wq = (const float*)d_in[1];
    const float* bq = (const float*)d_in[2];
    const float* Wk = (const float*)d_in[3];
    const float* bk = (const float*)d_in[4];
    const float* Wv = (const float*)d_in[5];
    const float* bv = (const float*)d_in[6];
    float* out = (float*)d_out;

    qkv_mma<<<dim3(HID / 128, TOKS / 128, 3), 256>>>(hidden, Wq, bq, Wk, bk, Wv, bv);

    cudaFuncSetAttribute(attn_mma, cudaFuncAttributeMaxDynamicSharedMemorySize, ATTN_SMEM);
    attn_mma<<<dim3(SEQ / 128, BATCH * NHEADS), 256, ATTN_SMEM>>>(out);
}